// round 5
// baseline (speedup 1.0000x reference)
#include <cuda_runtime.h>
#include <cuda_bf16.h>

#define NN 50000
#define NE 800000
#define NG 512
#define DN 64
#define DE 32

// Scratch (allocation-free: __device__ globals)
__device__ float g_AB[NN * 256];   // per-node projections: af|bf|as|bs (64 each)
__device__ float g_h1[NN * DN];
__device__ float g_h2[NN * DN];

// ---------------------------------------------------------------------------
// Node projection: AB[i][cb*64 + j] = sum_k h[i][k] * B_cb[k][j]
//   cb=0: Wf[k][j]      (af)   cb=1: Wf[64+k][j] (bf)
//   cb=2: Ws[k][j]      (as)   cb=3: Ws[64+k][j] (bs)
// Tiled GEMM: 64 nodes x 64 cols per block, K=64 fully staged, 4x4 microtile.
// ---------------------------------------------------------------------------
__global__ void __launch_bounds__(256) proj_kernel(
    const float* __restrict__ h, const float* __restrict__ Wf,
    const float* __restrict__ Ws, float* __restrict__ AB)
{
    __shared__ float As[64][65];  // transposed: As[k][n]
    __shared__ float Bs[64][64];  // Bs[k][j]

    const int tid = threadIdx.x;
    const int node0 = blockIdx.x * 64;
    const int cb = blockIdx.y;

    const float* Wsrc = (cb < 2) ? Wf : Ws;
    const int rowoff = (cb & 1) ? 64 : 0;

#pragma unroll
    for (int t = 0; t < 16; t++) {
        int lin = t * 256 + tid;
        int k = lin >> 6, j = lin & 63;
        Bs[k][j] = Wsrc[(rowoff + k) * 64 + j];
    }
#pragma unroll
    for (int t = 0; t < 16; t++) {
        int lin = t * 256 + tid;
        int n = lin >> 6, k = lin & 63;
        int node = node0 + n;
        As[k][n] = (node < NN) ? h[node * 64 + k] : 0.0f;
    }
    __syncthreads();

    const int tx = tid & 15;   // col group (4 cols)
    const int ty = tid >> 4;   // node group (4 nodes)
    float acc[4][4] = {};

#pragma unroll
    for (int k = 0; k < 64; k++) {
        float4 b4 = *(const float4*)&Bs[k][tx * 4];
        float a0 = As[k][ty * 4 + 0];
        float a1 = As[k][ty * 4 + 1];
        float a2 = As[k][ty * 4 + 2];
        float a3 = As[k][ty * 4 + 3];
        acc[0][0] += a0 * b4.x; acc[0][1] += a0 * b4.y; acc[0][2] += a0 * b4.z; acc[0][3] += a0 * b4.w;
        acc[1][0] += a1 * b4.x; acc[1][1] += a1 * b4.y; acc[1][2] += a1 * b4.z; acc[1][3] += a1 * b4.w;
        acc[2][0] += a2 * b4.x; acc[2][1] += a2 * b4.y; acc[2][2] += a2 * b4.z; acc[2][3] += a2 * b4.w;
        acc[3][0] += a3 * b4.x; acc[3][1] += a3 * b4.y; acc[3][2] += a3 * b4.z; acc[3][3] += a3 * b4.w;
    }

#pragma unroll
    for (int i = 0; i < 4; i++) {
        int node = node0 + ty * 4 + i;
        if (node < NN) {
            float4 o = make_float4(acc[i][0], acc[i][1], acc[i][2], acc[i][3]);
            *(float4*)&AB[(size_t)node * 256 + cb * 64 + tx * 4] = o;
        }
    }
}

// ---------------------------------------------------------------------------
// Edge kernel: one warp per edge (warp-stride). Lane handles channels 2l,2l+1.
// W_bot (rows 128..159) register-resident as f32x2 pairs; e broadcast via shfl;
// packed fma.rn.f32x2; fused sigmoid*softplus; red.global.add.v2.f32 scatter.
// NOTE: edge_index / batch are int32 (JAX x64 disabled -> int64 request
// silently becomes int32).
// ---------------------------------------------------------------------------
__device__ __forceinline__ float sigmoidf_(float x) {
    return 1.0f / (1.0f + __expf(-x));
}
__device__ __forceinline__ float softplusf_(float x) {
    float ax = fabsf(x);
    return fmaxf(x, 0.0f) + log1pf(__expf(-ax));
}

__global__ void __launch_bounds__(128, 2) edge_kernel(
    const int* __restrict__ ei, const float* __restrict__ ea,
    const float* __restrict__ AB, const float* __restrict__ Wf,
    const float* __restrict__ Ws, const float* __restrict__ bfv,
    const float* __restrict__ bsv, float* __restrict__ hout)
{
    const int lane = threadIdx.x & 31;
    const int warp = blockIdx.x * (blockDim.x >> 5) + (threadIdx.x >> 5);
    const int nwarps = gridDim.x * (blockDim.x >> 5);

    // Register-resident bottom weights: wf[k] = {Wf[128+k][2l], Wf[128+k][2l+1]}
    unsigned long long wf[32], ws[32];
#pragma unroll
    for (int k = 0; k < 32; k++) {
        wf[k] = *(const unsigned long long*)(Wf + (size_t)(128 + k) * 64 + 2 * lane);
        ws[k] = *(const unsigned long long*)(Ws + (size_t)(128 + k) * 64 + 2 * lane);
    }
    const float bf0 = bfv[2 * lane], bf1 = bfv[2 * lane + 1];
    const float bs0 = bsv[2 * lane], bs1 = bsv[2 * lane + 1];

    for (int e = warp; e < NE; e += nwarps) {
        const int src = ei[e];
        const int dst = ei[NE + e];
        const float ev = ea[(size_t)e * 32 + lane];

        const float* pd = AB + (size_t)dst * 256 + 2 * lane;
        const float* ps = AB + (size_t)src * 256 + 2 * lane;
        float2 af = *(const float2*)(pd);
        float2 bfp = *(const float2*)(ps + 64);
        float2 as2 = *(const float2*)(pd + 128);
        float2 bsp = *(const float2*)(ps + 192);

        unsigned long long accf = 0ULL, accs = 0ULL;
#pragma unroll
        for (int k = 0; k < 32; k++) {
            float ek = __shfl_sync(0xffffffffu, ev, k);
            unsigned long long ek2;
            asm("mov.b64 %0, {%1, %2};" : "=l"(ek2) : "f"(ek), "f"(ek));
            asm("fma.rn.f32x2 %0, %1, %2, %3;"
                : "=l"(accf) : "l"(ek2), "l"(wf[k]), "l"(accf));
            asm("fma.rn.f32x2 %0, %1, %2, %3;"
                : "=l"(accs) : "l"(ek2), "l"(ws[k]), "l"(accs));
        }
        float ef0, ef1, es0, es1;
        asm("mov.b64 {%0, %1}, %2;" : "=f"(ef0), "=f"(ef1) : "l"(accf));
        asm("mov.b64 {%0, %1}, %2;" : "=f"(es0), "=f"(es1) : "l"(accs));

        float pf0 = af.x + bfp.x + ef0 + bf0;
        float pf1 = af.y + bfp.y + ef1 + bf1;
        float q0  = as2.x + bsp.x + es0 + bs0;
        float q1  = as2.y + bsp.y + es1 + bs1;

        float m0 = sigmoidf_(pf0) * softplusf_(q0);
        float m1 = sigmoidf_(pf1) * softplusf_(q1);

        float* outp = hout + (size_t)dst * 64 + 2 * lane;
        asm volatile("red.global.add.v2.f32 [%0], {%1, %2};"
                     :: "l"(outp), "f"(m0), "f"(m1) : "memory");
    }
}

// ---------------------------------------------------------------------------
// Output: out[g] = b_out; then per node i: out[batch[i]] += h2[i] . W_out
// ---------------------------------------------------------------------------
__global__ void init_out_kernel(float* __restrict__ out, const float* __restrict__ b_out)
{
    int t = threadIdx.x;
    if (t < NG) out[t] = b_out[0];
}

__global__ void __launch_bounds__(256) pool_kernel(
    const float* __restrict__ h2, const int* __restrict__ batch,
    const float* __restrict__ Wout, float* __restrict__ out)
{
    const int warp = blockIdx.x * (blockDim.x >> 5) + (threadIdx.x >> 5);
    const int lane = threadIdx.x & 31;
    if (warp >= NN) return;
    float2 v = *(const float2*)(h2 + (size_t)warp * 64 + 2 * lane);
    float s = v.x * Wout[2 * lane] + v.y * Wout[2 * lane + 1];
#pragma unroll
    for (int off = 16; off; off >>= 1)
        s += __shfl_down_sync(0xffffffffu, s, off);
    if (lane == 0) atomicAdd(&out[batch[warp]], s);
}

// ---------------------------------------------------------------------------
extern "C" void kernel_launch(void* const* d_in, const int* in_sizes, int n_in,
                              void* d_out, int out_size)
{
    const float* x     = (const float*)d_in[0];
    const int*   ei    = (const int*)d_in[1];
    const float* ea    = (const float*)d_in[2];
    const int*   batch = (const int*)d_in[3];
    const float* Wf1  = (const float*)d_in[4];
    const float* bf1  = (const float*)d_in[5];
    const float* Ws1  = (const float*)d_in[6];
    const float* bs1  = (const float*)d_in[7];
    const float* Wf2  = (const float*)d_in[8];
    const float* bf2  = (const float*)d_in[9];
    const float* Ws2  = (const float*)d_in[10];
    const float* bs2  = (const float*)d_in[11];
    const float* Wout = (const float*)d_in[12];
    const float* bout = (const float*)d_in[13];
    float* out = (float*)d_out;

    float *AB, *h1, *h2;
    cudaGetSymbolAddress((void**)&AB, g_AB);
    cudaGetSymbolAddress((void**)&h1, g_h1);
    cudaGetSymbolAddress((void**)&h2, g_h2);

    const dim3 pgrid((NN + 63) / 64, 4);

    // ---- Layer 1 ----
    proj_kernel<<<pgrid, 256>>>(x, Wf1, Ws1, AB);
    cudaMemcpyAsync(h1, x, (size_t)NN * DN * sizeof(float),
                    cudaMemcpyDeviceToDevice);
    edge_kernel<<<1184, 128>>>(ei, ea, AB, Wf1, Ws1, bf1, bs1, h1);

    // ---- Layer 2 ----
    proj_kernel<<<pgrid, 256>>>(h1, Wf2, Ws2, AB);
    cudaMemcpyAsync(h2, h1, (size_t)NN * DN * sizeof(float),
                    cudaMemcpyDeviceToDevice);
    edge_kernel<<<1184, 128>>>(ei, ea, AB, Wf2, Ws2, bf2, bs2, h2);

    // ---- Pool + readout ----
    init_out_kernel<<<1, 512>>>(out, bout);
    pool_kernel<<<NN / 8, 256>>>(h2, batch, Wout, out);
}

// round 6
// speedup vs baseline: 1.6221x; 1.6221x over previous
#include <cuda_runtime.h>
#include <cuda_bf16.h>

#define NN 50000
#define NE 800000
#define NG 512
#define DN 64
#define DE 32
#define EB 4   // edges per warp batch (NE % EB == 0 required)

// Scratch (allocation-free: __device__ globals)
__device__ float g_AB[NN * 256];   // per-node projections: af|bf|as|bs (64 each)
__device__ float g_h1[NN * DN];
__device__ float g_h2[NN * DN];

// ---------------------------------------------------------------------------
// Node projection: AB[i][cb*64 + j] = sum_k h[i][k] * B_cb[k][j]  (+ bias fold)
//   cb=0: Wf[k][j] + bf[j]   (af, f-bias folded)
//   cb=1: Wf[64+k][j]        (bf)
//   cb=2: Ws[k][j] + bs[j]   (as, s-bias folded)
//   cb=3: Ws[64+k][j]        (bs)
// ---------------------------------------------------------------------------
__global__ void __launch_bounds__(256) proj_kernel(
    const float* __restrict__ h, const float* __restrict__ Wf,
    const float* __restrict__ Ws, const float* __restrict__ bfv,
    const float* __restrict__ bsv, float* __restrict__ AB)
{
    __shared__ float As[64][65];  // transposed: As[k][n]
    __shared__ float Bs[64][64];  // Bs[k][j]

    const int tid = threadIdx.x;
    const int node0 = blockIdx.x * 64;
    const int cb = blockIdx.y;

    const float* Wsrc = (cb < 2) ? Wf : Ws;
    const int rowoff = (cb & 1) ? 64 : 0;

#pragma unroll
    for (int t = 0; t < 16; t++) {
        int lin = t * 256 + tid;
        int k = lin >> 6, j = lin & 63;
        Bs[k][j] = Wsrc[(rowoff + k) * 64 + j];
    }
#pragma unroll
    for (int t = 0; t < 16; t++) {
        int lin = t * 256 + tid;
        int n = lin >> 6, k = lin & 63;
        int node = node0 + n;
        As[k][n] = (node < NN) ? h[node * 64 + k] : 0.0f;
    }
    __syncthreads();

    const int tx = tid & 15;   // col group (4 cols)
    const int ty = tid >> 4;   // node group (4 nodes)
    float acc[4][4] = {};

#pragma unroll
    for (int k = 0; k < 64; k++) {
        float4 b4 = *(const float4*)&Bs[k][tx * 4];
        float a0 = As[k][ty * 4 + 0];
        float a1 = As[k][ty * 4 + 1];
        float a2 = As[k][ty * 4 + 2];
        float a3 = As[k][ty * 4 + 3];
        acc[0][0] += a0 * b4.x; acc[0][1] += a0 * b4.y; acc[0][2] += a0 * b4.z; acc[0][3] += a0 * b4.w;
        acc[1][0] += a1 * b4.x; acc[1][1] += a1 * b4.y; acc[1][2] += a1 * b4.z; acc[1][3] += a1 * b4.w;
        acc[2][0] += a2 * b4.x; acc[2][1] += a2 * b4.y; acc[2][2] += a2 * b4.z; acc[2][3] += a2 * b4.w;
        acc[3][0] += a3 * b4.x; acc[3][1] += a3 * b4.y; acc[3][2] += a3 * b4.z; acc[3][3] += a3 * b4.w;
    }

    // Bias fold: cb=0 gets bf[j], cb=2 gets bs[j]
    float bias[4] = {0.f, 0.f, 0.f, 0.f};
    if (cb == 0) {
#pragma unroll
        for (int j = 0; j < 4; j++) bias[j] = bfv[tx * 4 + j];
    } else if (cb == 2) {
#pragma unroll
        for (int j = 0; j < 4; j++) bias[j] = bsv[tx * 4 + j];
    }

#pragma unroll
    for (int i = 0; i < 4; i++) {
        int node = node0 + ty * 4 + i;
        if (node < NN) {
            float4 o = make_float4(acc[i][0] + bias[0], acc[i][1] + bias[1],
                                   acc[i][2] + bias[2], acc[i][3] + bias[3]);
            *(float4*)&AB[(size_t)node * 256 + cb * 64 + tx * 4] = o;
        }
    }
}

// ---------------------------------------------------------------------------
// Edge kernel: one warp per EB edges. Lane handles channels 2l,2l+1.
// W_bot register-resident as f32x2 pairs. All gathers for the batch issued
// before any compute (MLP=EB*4+EB). Packed fma.rn.f32x2; fused
// sigmoid*softplus; red.global.add.v2.f32 scatter. edge_index is int32.
// ---------------------------------------------------------------------------
__device__ __forceinline__ float sigmoidf_(float x) {
    return 1.0f / (1.0f + __expf(-x));
}
__device__ __forceinline__ float softplusf_(float x) {
    float ax = fabsf(x);
    return fmaxf(x, 0.0f) + log1pf(__expf(-ax));
}

__global__ void __launch_bounds__(128, 2) edge_kernel(
    const int* __restrict__ ei, const float* __restrict__ ea,
    const float* __restrict__ AB, const float* __restrict__ Wf,
    const float* __restrict__ Ws, float* __restrict__ hout)
{
    const int lane = threadIdx.x & 31;
    const int warp = blockIdx.x * (blockDim.x >> 5) + (threadIdx.x >> 5);
    const int nwarps = gridDim.x * (blockDim.x >> 5);

    // Register-resident bottom weights: wf[k] = {Wf[128+k][2l], Wf[128+k][2l+1]}
    unsigned long long wf[32], ws[32];
#pragma unroll
    for (int k = 0; k < 32; k++) {
        wf[k] = *(const unsigned long long*)(Wf + (size_t)(128 + k) * 64 + 2 * lane);
        ws[k] = *(const unsigned long long*)(Ws + (size_t)(128 + k) * 64 + 2 * lane);
    }

    // NE % EB == 0 and start/stride are multiples of EB -> every batch is full.
    for (int e0 = warp * EB; e0 < NE; e0 += nwarps * EB) {
        int   srcs[EB], dsts[EB];
        float evs[EB];
        float2 afv[EB], bfpv[EB], as2v[EB], bspv[EB];

        // --- Issue ALL loads for the batch up front (maximize MLP) ---
#pragma unroll
        for (int i = 0; i < EB; i++) {
            srcs[i] = ei[e0 + i];
            dsts[i] = ei[NE + e0 + i];
        }
#pragma unroll
        for (int i = 0; i < EB; i++)
            evs[i] = ea[(size_t)(e0 + i) * 32 + lane];
#pragma unroll
        for (int i = 0; i < EB; i++) {
            const float* pd = AB + (size_t)dsts[i] * 256 + 2 * lane;
            const float* ps = AB + (size_t)srcs[i] * 256 + 2 * lane;
            afv[i]  = *(const float2*)(pd);
            bfpv[i] = *(const float2*)(ps + 64);
            as2v[i] = *(const float2*)(pd + 128);
            bspv[i] = *(const float2*)(ps + 192);
        }

        // --- Compute each edge ---
#pragma unroll
        for (int i = 0; i < EB; i++) {
            unsigned long long accf = 0ULL, accs = 0ULL;
#pragma unroll
            for (int k = 0; k < 32; k++) {
                float ek = __shfl_sync(0xffffffffu, evs[i], k);
                unsigned long long ek2;
                asm("mov.b64 %0, {%1, %2};" : "=l"(ek2) : "f"(ek), "f"(ek));
                asm("fma.rn.f32x2 %0, %1, %2, %3;"
                    : "=l"(accf) : "l"(ek2), "l"(wf[k]), "l"(accf));
                asm("fma.rn.f32x2 %0, %1, %2, %3;"
                    : "=l"(accs) : "l"(ek2), "l"(ws[k]), "l"(accs));
            }
            float ef0, ef1, es0, es1;
            asm("mov.b64 {%0, %1}, %2;" : "=f"(ef0), "=f"(ef1) : "l"(accf));
            asm("mov.b64 {%0, %1}, %2;" : "=f"(es0), "=f"(es1) : "l"(accs));

            // biases already folded into af / as blocks by proj_kernel
            float pf0 = afv[i].x + bfpv[i].x + ef0;
            float pf1 = afv[i].y + bfpv[i].y + ef1;
            float q0  = as2v[i].x + bspv[i].x + es0;
            float q1  = as2v[i].y + bspv[i].y + es1;

            float m0 = sigmoidf_(pf0) * softplusf_(q0);
            float m1 = sigmoidf_(pf1) * softplusf_(q1);

            float* outp = hout + (size_t)dsts[i] * 64 + 2 * lane;
            asm volatile("red.global.add.v2.f32 [%0], {%1, %2};"
                         :: "l"(outp), "f"(m0), "f"(m1) : "memory");
        }
    }
}

// ---------------------------------------------------------------------------
// Output: out[g] = b_out; then per node i: out[batch[i]] += h2[i] . W_out
// ---------------------------------------------------------------------------
__global__ void init_out_kernel(float* __restrict__ out, const float* __restrict__ b_out)
{
    int t = threadIdx.x;
    if (t < NG) out[t] = b_out[0];
}

__global__ void __launch_bounds__(256) pool_kernel(
    const float* __restrict__ h2, const int* __restrict__ batch,
    const float* __restrict__ Wout, float* __restrict__ out)
{
    const int warp = blockIdx.x * (blockDim.x >> 5) + (threadIdx.x >> 5);
    const int lane = threadIdx.x & 31;
    if (warp >= NN) return;
    float2 v = *(const float2*)(h2 + (size_t)warp * 64 + 2 * lane);
    float s = v.x * Wout[2 * lane] + v.y * Wout[2 * lane + 1];
#pragma unroll
    for (int off = 16; off; off >>= 1)
        s += __shfl_down_sync(0xffffffffu, s, off);
    if (lane == 0) atomicAdd(&out[batch[warp]], s);
}

// ---------------------------------------------------------------------------
extern "C" void kernel_launch(void* const* d_in, const int* in_sizes, int n_in,
                              void* d_out, int out_size)
{
    const float* x     = (const float*)d_in[0];
    const int*   ei    = (const int*)d_in[1];
    const float* ea    = (const float*)d_in[2];
    const int*   batch = (const int*)d_in[3];
    const float* Wf1  = (const float*)d_in[4];
    const float* bf1  = (const float*)d_in[5];
    const float* Ws1  = (const float*)d_in[6];
    const float* bs1  = (const float*)d_in[7];
    const float* Wf2  = (const float*)d_in[8];
    const float* bf2  = (const float*)d_in[9];
    const float* Ws2  = (const float*)d_in[10];
    const float* bs2  = (const float*)d_in[11];
    const float* Wout = (const float*)d_in[12];
    const float* bout = (const float*)d_in[13];
    float* out = (float*)d_out;

    float *AB, *h1, *h2;
    cudaGetSymbolAddress((void**)&AB, g_AB);
    cudaGetSymbolAddress((void**)&h1, g_h1);
    cudaGetSymbolAddress((void**)&h2, g_h2);

    const dim3 pgrid((NN + 63) / 64, 4);

    // ---- Layer 1 ----
    proj_kernel<<<pgrid, 256>>>(x, Wf1, Ws1, bf1, bs1, AB);
    cudaMemcpyAsync(h1, x, (size_t)NN * DN * sizeof(float),
                    cudaMemcpyDeviceToDevice);
    edge_kernel<<<296, 128>>>(ei, ea, AB, Wf1, Ws1, h1);

    // ---- Layer 2 ----
    proj_kernel<<<pgrid, 256>>>(h1, Wf2, Ws2, bf2, bs2, AB);
    cudaMemcpyAsync(h2, h1, (size_t)NN * DN * sizeof(float),
                    cudaMemcpyDeviceToDevice);
    edge_kernel<<<296, 128>>>(ei, ea, AB, Wf2, Ws2, h2);

    // ---- Pool + readout ----
    init_out_kernel<<<1, 512>>>(out, bout);
    pool_kernel<<<NN / 8, 256>>>(h2, batch, Wout, out);
}

// round 7
// speedup vs baseline: 1.8715x; 1.1538x over previous
#include <cuda_runtime.h>
#include <cuda_bf16.h>

#define NN 50000
#define NE 800000
#define NG 512
#define DN 64
#define DE 32
#define EB 8   // edges per warp batch (NE % EB == 0)

// Scratch (allocation-free: __device__ globals)
// ABd[node][128]: interleaved {af[2l],af[2l+1],as[2l],as[2l+1]} per lane l (dst gather)
// ABs[node][128]: interleaved {bf[2l],bf[2l+1],bs[2l],bs[2l+1]} per lane l (src gather)
__device__ float g_ABd[NN * 128];
__device__ float g_ABs[NN * 128];
__device__ float g_h1[NN * DN];
__device__ float g_h2[NN * DN];

// ---------------------------------------------------------------------------
// Node projection into interleaved gather layout (+ bias fold).
//   cb=0: af[j] = h·Wf[0:64]  + bf[j]  -> ABd slot 0/1
//   cb=1: bf[j] = h·Wf[64:128]         -> ABs slot 0/1
//   cb=2: as[j] = h·Ws[0:64]  + bs[j]  -> ABd slot 2/3
//   cb=3: bs[j] = h·Ws[64:128]         -> ABs slot 2/3
// ---------------------------------------------------------------------------
__global__ void __launch_bounds__(256) proj_kernel(
    const float* __restrict__ h, const float* __restrict__ Wf,
    const float* __restrict__ Ws, const float* __restrict__ bfv,
    const float* __restrict__ bsv, float* __restrict__ ABd,
    float* __restrict__ ABs)
{
    __shared__ float As[64][65];  // transposed: As[k][n]
    __shared__ float Bs[64][64];  // Bs[k][j]

    const int tid = threadIdx.x;
    const int node0 = blockIdx.x * 64;
    const int cb = blockIdx.y;

    const float* Wsrc = (cb < 2) ? Wf : Ws;
    const int rowoff = (cb & 1) ? 64 : 0;

#pragma unroll
    for (int t = 0; t < 16; t++) {
        int lin = t * 256 + tid;
        int k = lin >> 6, j = lin & 63;
        Bs[k][j] = Wsrc[(rowoff + k) * 64 + j];
    }
#pragma unroll
    for (int t = 0; t < 16; t++) {
        int lin = t * 256 + tid;
        int n = lin >> 6, k = lin & 63;
        int node = node0 + n;
        As[k][n] = (node < NN) ? h[node * 64 + k] : 0.0f;
    }
    __syncthreads();

    const int tx = tid & 15;   // col group (4 cols)
    const int ty = tid >> 4;   // node group (4 nodes)
    float acc[4][4] = {};

#pragma unroll
    for (int k = 0; k < 64; k++) {
        float4 b4 = *(const float4*)&Bs[k][tx * 4];
        float a0 = As[k][ty * 4 + 0];
        float a1 = As[k][ty * 4 + 1];
        float a2 = As[k][ty * 4 + 2];
        float a3 = As[k][ty * 4 + 3];
        acc[0][0] += a0 * b4.x; acc[0][1] += a0 * b4.y; acc[0][2] += a0 * b4.z; acc[0][3] += a0 * b4.w;
        acc[1][0] += a1 * b4.x; acc[1][1] += a1 * b4.y; acc[1][2] += a1 * b4.z; acc[1][3] += a1 * b4.w;
        acc[2][0] += a2 * b4.x; acc[2][1] += a2 * b4.y; acc[2][2] += a2 * b4.z; acc[2][3] += a2 * b4.w;
        acc[3][0] += a3 * b4.x; acc[3][1] += a3 * b4.y; acc[3][2] += a3 * b4.z; acc[3][3] += a3 * b4.w;
    }

    // Bias fold: cb=0 gets bf[j], cb=2 gets bs[j]
    float bias[4] = {0.f, 0.f, 0.f, 0.f};
    if (cb == 0) {
#pragma unroll
        for (int j = 0; j < 4; j++) bias[j] = bfv[tx * 4 + j];
    } else if (cb == 2) {
#pragma unroll
        for (int j = 0; j < 4; j++) bias[j] = bsv[tx * 4 + j];
    }

    float* outbase = (cb == 0 || cb == 2) ? ABd : ABs;
    const int sub = (cb >= 2) ? 2 : 0;  // slot within the {f,f,s,s} quad

#pragma unroll
    for (int i = 0; i < 4; i++) {
        int node = node0 + ty * 4 + i;
        if (node < NN) {
            // j = tx*4 + {0,1} -> pair 2tx;  j = tx*4 + {2,3} -> pair 2tx+1
            float2 lo = make_float2(acc[i][0] + bias[0], acc[i][1] + bias[1]);
            float2 hi = make_float2(acc[i][2] + bias[2], acc[i][3] + bias[3]);
            *(float2*)&outbase[(size_t)node * 128 + (2 * tx + 0) * 4 + sub] = lo;
            *(float2*)&outbase[(size_t)node * 128 + (2 * tx + 1) * 4 + sub] = hi;
        }
    }
}

// ---------------------------------------------------------------------------
// Edge kernel: one warp per EB edges. Lane handles channels 2l,2l+1.
// W_bot register-resident as f32x2 pairs. Edge-attr values staged to smem as
// DUPLICATED {e,e} pairs -> inner loop is ld.shared.b64 + 2x fma.rn.f32x2
// (no shfl, no pack). Gathers are 2x float4 per edge (fused layout), all
// issued before compute. red.global.add.v2.f32 scatter. edge_index is int32.
// ---------------------------------------------------------------------------
__device__ __forceinline__ float sigmoidf_(float x) {
    return 1.0f / (1.0f + __expf(-x));
}
__device__ __forceinline__ float softplusf_(float x) {
    float ax = fabsf(x);
    float em = __expf(-ax);
    return fmaxf(x, 0.0f) + __logf(1.0f + em);
}

__global__ void __launch_bounds__(128, 2) edge_kernel(
    const int* __restrict__ ei, const float* __restrict__ ea,
    const float* __restrict__ ABd, const float* __restrict__ ABs,
    const float* __restrict__ Wf, const float* __restrict__ Ws,
    float* __restrict__ hout)
{
    __shared__ float2 edup[4][EB][32];

    const int lane = threadIdx.x & 31;
    const int wslot = threadIdx.x >> 5;
    const int warp = blockIdx.x * 4 + wslot;
    const int nwarps = gridDim.x * 4;

    // Register-resident bottom weights: wf[k] = {Wf[128+k][2l], Wf[128+k][2l+1]}
    unsigned long long wf[32], ws[32];
#pragma unroll
    for (int k = 0; k < 32; k++) {
        wf[k] = *(const unsigned long long*)(Wf + (size_t)(128 + k) * 64 + 2 * lane);
        ws[k] = *(const unsigned long long*)(Ws + (size_t)(128 + k) * 64 + 2 * lane);
    }

    const unsigned ebase =
        (unsigned)__cvta_generic_to_shared(&edup[wslot][0][0]);

    for (int e0 = warp * EB; e0 < NE; e0 += nwarps * EB) {
        int    srcs[EB], dsts[EB];
        float4 d4[EB], s4[EB];

        // --- Issue ALL loads for the batch up front (maximize MLP) ---
#pragma unroll
        for (int i = 0; i < EB; i++) {
            srcs[i] = ei[e0 + i];
            dsts[i] = ei[NE + e0 + i];
        }
#pragma unroll
        for (int i = 0; i < EB; i++) {
            float ev = ea[(size_t)(e0 + i) * 32 + lane];
            asm volatile("st.shared.v2.f32 [%0], {%1, %1};"
                         :: "r"(ebase + (unsigned)((i * 32 + lane) * 8)), "f"(ev));
        }
#pragma unroll
        for (int i = 0; i < EB; i++) {
            d4[i] = *(const float4*)(ABd + (size_t)dsts[i] * 128 + lane * 4);
            s4[i] = *(const float4*)(ABs + (size_t)srcs[i] * 128 + lane * 4);
        }
        __syncwarp();

        // --- Compute each edge ---
#pragma unroll
        for (int i = 0; i < EB; i++) {
            unsigned long long accf = 0ULL, accs = 0ULL;
#pragma unroll
            for (int k = 0; k < 32; k++) {
                unsigned long long ek2;
                asm volatile("ld.shared.b64 %0, [%1];"
                             : "=l"(ek2)
                             : "r"(ebase + (unsigned)((i * 32 + k) * 8)));
                asm("fma.rn.f32x2 %0, %1, %2, %3;"
                    : "=l"(accf) : "l"(ek2), "l"(wf[k]), "l"(accf));
                asm("fma.rn.f32x2 %0, %1, %2, %3;"
                    : "=l"(accs) : "l"(ek2), "l"(ws[k]), "l"(accs));
            }
            float ef0, ef1, es0, es1;
            asm("mov.b64 {%0, %1}, %2;" : "=f"(ef0), "=f"(ef1) : "l"(accf));
            asm("mov.b64 {%0, %1}, %2;" : "=f"(es0), "=f"(es1) : "l"(accs));

            // biases already folded into af / as by proj_kernel
            float pf0 = d4[i].x + s4[i].x + ef0;
            float pf1 = d4[i].y + s4[i].y + ef1;
            float q0  = d4[i].z + s4[i].z + es0;
            float q1  = d4[i].w + s4[i].w + es1;

            float m0 = sigmoidf_(pf0) * softplusf_(q0);
            float m1 = sigmoidf_(pf1) * softplusf_(q1);

            float* outp = hout + (size_t)dsts[i] * 64 + 2 * lane;
            asm volatile("red.global.add.v2.f32 [%0], {%1, %2};"
                         :: "l"(outp), "f"(m0), "f"(m1) : "memory");
        }
        __syncwarp();  // protect edup before next batch overwrites
    }
}

// ---------------------------------------------------------------------------
// Output: out[g] = b_out; then per node i: out[batch[i]] += h2[i] . W_out
// ---------------------------------------------------------------------------
__global__ void init_out_kernel(float* __restrict__ out, const float* __restrict__ b_out)
{
    int t = threadIdx.x;
    if (t < NG) out[t] = b_out[0];
}

__global__ void __launch_bounds__(256) pool_kernel(
    const float* __restrict__ h2, const int* __restrict__ batch,
    const float* __restrict__ Wout, float* __restrict__ out)
{
    const int warp = blockIdx.x * (blockDim.x >> 5) + (threadIdx.x >> 5);
    const int lane = threadIdx.x & 31;
    if (warp >= NN) return;
    float2 v = *(const float2*)(h2 + (size_t)warp * 64 + 2 * lane);
    float s = v.x * Wout[2 * lane] + v.y * Wout[2 * lane + 1];
#pragma unroll
    for (int off = 16; off; off >>= 1)
        s += __shfl_down_sync(0xffffffffu, s, off);
    if (lane == 0) atomicAdd(&out[batch[warp]], s);
}

// ---------------------------------------------------------------------------
extern "C" void kernel_launch(void* const* d_in, const int* in_sizes, int n_in,
                              void* d_out, int out_size)
{
    const float* x     = (const float*)d_in[0];
    const int*   ei    = (const int*)d_in[1];
    const float* ea    = (const float*)d_in[2];
    const int*   batch = (const int*)d_in[3];
    const float* Wf1  = (const float*)d_in[4];
    const float* bf1  = (const float*)d_in[5];
    const float* Ws1  = (const float*)d_in[6];
    const float* bs1  = (const float*)d_in[7];
    const float* Wf2  = (const float*)d_in[8];
    const float* bf2  = (const float*)d_in[9];
    const float* Ws2  = (const float*)d_in[10];
    const float* bs2  = (const float*)d_in[11];
    const float* Wout = (const float*)d_in[12];
    const float* bout = (const float*)d_in[13];
    float* out = (float*)d_out;

    float *ABd, *ABs, *h1, *h2;
    cudaGetSymbolAddress((void**)&ABd, g_ABd);
    cudaGetSymbolAddress((void**)&ABs, g_ABs);
    cudaGetSymbolAddress((void**)&h1, g_h1);
    cudaGetSymbolAddress((void**)&h2, g_h2);

    const dim3 pgrid((NN + 63) / 64, 4);

    // ---- Layer 1 ----
    proj_kernel<<<pgrid, 256>>>(x, Wf1, Ws1, bf1, bs1, ABd, ABs);
    cudaMemcpyAsync(h1, x, (size_t)NN * DN * sizeof(float),
                    cudaMemcpyDeviceToDevice);
    edge_kernel<<<296, 128>>>(ei, ea, ABd, ABs, Wf1, Ws1, h1);

    // ---- Layer 2 ----
    proj_kernel<<<pgrid, 256>>>(h1, Wf2, Ws2, bf2, bs2, ABd, ABs);
    cudaMemcpyAsync(h2, h1, (size_t)NN * DN * sizeof(float),
                    cudaMemcpyDeviceToDevice);
    edge_kernel<<<296, 128>>>(ei, ea, ABd, ABs, Wf2, Ws2, h2);

    // ---- Pool + readout ----
    init_out_kernel<<<1, 512>>>(out, bout);
    pool_kernel<<<NN / 8, 256>>>(h2, batch, Wout, out);
}